// round 3
// baseline (speedup 1.0000x reference)
#include <cuda_runtime.h>
#include <cstdint>

// Problem geometry (fixed by the reference):
//   src:    [16,32,256,256] f32  -> 512 rows x 65536 elements
//   labels: same shape, int32 (jax downgrades int64 without x64), in [0,512)
//   out:    per-row segment mean gathered back to each position.
#define NUM_ROWS   512
#define ROW_N      65536
#define NUM_LABELS 512
#define TOTAL_ELEMS (NUM_ROWS * ROW_N)   // 33554432

// Scratch (allocation-free rule: __device__ global).
// {sum, count} per (row, label): 512*512*8B = 2 MB, L2-resident.
// Re-zeroed at the start of every launch (graph replays reuse module state).
__device__ float2 g_bins[NUM_ROWS * NUM_LABELS];

// One 8B vector reduction adds {val, 1.0f} to {sum, count} (sm_90+).
__device__ __forceinline__ void red_sum_count(float2* p, float v) {
    asm volatile("red.global.add.v2.f32 [%0], {%1, %2};"
                 :: "l"(p), "f"(v), "f"(1.0f)
                 : "memory");
}

// ---------------------------------------------------------------------------
// Kernel 0: zero the accumulation bins (262144 float2).
// ---------------------------------------------------------------------------
__global__ void sppool_zero_bins() {
    unsigned i = blockIdx.x * blockDim.x + threadIdx.x;
    if (i < NUM_ROWS * NUM_LABELS)
        g_bins[i] = make_float2(0.0f, 0.0f);
}

// ---------------------------------------------------------------------------
// Kernel 1: scatter. Each thread handles 4 consecutive elements (same row:
// ROW_N % 4 == 0 and groups are aligned). One LDG.128 for 4 int32 labels,
// one LDG.128 for 4 floats, four vector reds into the row's bins.
// ---------------------------------------------------------------------------
__global__ void __launch_bounds__(256)
sppool_scatter(const float* __restrict__ src, const int* __restrict__ labels) {
    unsigned gid  = blockIdx.x * blockDim.x + threadIdx.x;
    unsigned base = gid * 4u;                       // element index, < 2^25

    int4   l = *reinterpret_cast<const int4*>(labels + base);
    float4 s = *reinterpret_cast<const float4*>(src + base);

    unsigned row = base >> 16;                      // / ROW_N
    float2* bins = g_bins + row * NUM_LABELS;

    red_sum_count(bins + l.x, s.x);
    red_sum_count(bins + l.y, s.y);
    red_sum_count(bins + l.z, s.z);
    red_sum_count(bins + l.w, s.w);
}

// ---------------------------------------------------------------------------
// Kernel 2: gather. One CTA per row. 512 threads: each computes one segment
// mean into shared, then the CTA streams the row's 65536 labels (int4 = 16B
// loads) and writes the means (float4 stores). Empty bins give NaN (0/0) but
// are never gathered: any label present in the row has count >= 1.
// ---------------------------------------------------------------------------
__global__ void __launch_bounds__(512)
sppool_gather(const int* __restrict__ labels, float* __restrict__ out) {
    __shared__ float s_mean[NUM_LABELS];
    const unsigned row = blockIdx.x;
    const unsigned t   = threadIdx.x;

    float2 bc = g_bins[row * NUM_LABELS + t];
    s_mean[t] = bc.x / bc.y;
    __syncthreads();

    const int* lab = labels + (size_t)row * ROW_N;
    float*     o   = out    + (size_t)row * ROW_N;

    // 65536 / (512 threads * 4 per group) = 32 iterations, fully coalesced
    #pragma unroll
    for (int i = 0; i < 32; ++i) {
        unsigned idx = (i * 512u + t) * 4u;
        int4 p = *reinterpret_cast<const int4*>(lab + idx);
        float4 v;
        v.x = s_mean[p.x];
        v.y = s_mean[p.y];
        v.z = s_mean[p.z];
        v.w = s_mean[p.w];
        *reinterpret_cast<float4*>(o + idx) = v;
    }
}

// ---------------------------------------------------------------------------
// Launch: zero -> scatter -> gather (stream-ordered, graph-capturable).
// ---------------------------------------------------------------------------
extern "C" void kernel_launch(void* const* d_in, const int* in_sizes, int n_in,
                              void* d_out, int out_size) {
    const float* src    = (const float*)d_in[0];
    const int*   labels = (const int*)d_in[1];
    float*       out    = (float*)d_out;

    sppool_zero_bins<<<(NUM_ROWS * NUM_LABELS + 255) / 256, 256>>>();

    const unsigned n_vec4 = TOTAL_ELEMS / 4;              // 8388608
    sppool_scatter<<<n_vec4 / 256, 256>>>(src, labels);   // 32768 blocks

    sppool_gather<<<NUM_ROWS, 512>>>(labels, out);        // 512 blocks
}

// round 5
// speedup vs baseline: 1.6029x; 1.6029x over previous
#include <cuda_runtime.h>
#include <cstdint>

// Problem geometry (fixed by the reference):
//   src:    [16,32,256,256] f32  -> 512 rows x 65536 elements
//   labels: same shape, int32, values in [0,512)
//   out:    per-row segment mean gathered back to each position.
#define NUM_ROWS   512
#define ROW_N      65536
#define NUM_LABELS 512
#define TOTAL_ELEMS (NUM_ROWS * ROW_N)   // 33554432

// Elements per scatter CTA: 256 threads x 8 = 2048 -> 32 chunks per row.
#define SC_THREADS 256
#define SC_PER_THR 8
#define SC_CHUNK   (SC_THREADS * SC_PER_THR)      // 2048
#define SC_CHUNKS_PER_ROW (ROW_N / SC_CHUNK)      // 32

// Scratch (allocation-free rule: __device__ global).
// {sum, count} per (row, label): 512*512*8B = 2 MB, L2-resident.
__device__ float2 g_bins[NUM_ROWS * NUM_LABELS];

// One 8B vector reduction adds {val, 1.0f} to {sum, count} (sm_90+).
__device__ __forceinline__ void red_sum_count(float2* p, float v) {
    asm volatile("red.global.add.v2.f32 [%0], {%1, %2};"
                 :: "l"(p), "f"(v), "f"(1.0f)
                 : "memory");
}

// ---------------------------------------------------------------------------
// Kernel 0: zero the accumulation bins (262144 float2).
// ---------------------------------------------------------------------------
__global__ void sppool_zero_bins() {
    unsigned i = blockIdx.x * blockDim.x + threadIdx.x;
    if (i < NUM_ROWS * NUM_LABELS)
        g_bins[i] = make_float2(0.0f, 0.0f);
}

// ---------------------------------------------------------------------------
// Kernel 1: scatter.
// CTA -> work mapping is ROW-INTERLEAVED: row = blockIdx.x % 512. Consecutive
// (concurrently resident) CTAs therefore target DIFFERENT rows' 4KB bin
// regions, spreading concurrent L2 atomics across the full 2MB bin array and
// all LTS partitions instead of funneling ~1184 CTAs into ~18 rows.
// Each thread: 8 consecutive elements (2x LDG.128 labels, 2x LDG.128 src,
// 8 vector reds). Loads stay fully coalesced within the CTA.
// ---------------------------------------------------------------------------
__global__ void __launch_bounds__(SC_THREADS)
sppool_scatter(const float* __restrict__ src, const int* __restrict__ labels) {
    const unsigned row   = blockIdx.x & (NUM_ROWS - 1);      // % 512
    const unsigned chunk = blockIdx.x >> 9;                  // / 512
    const unsigned base  = row * ROW_N + chunk * SC_CHUNK + threadIdx.x * SC_PER_THR;

    int4   l0 = *reinterpret_cast<const int4*>(labels + base);
    int4   l1 = *reinterpret_cast<const int4*>(labels + base + 4);
    float4 s0 = *reinterpret_cast<const float4*>(src + base);
    float4 s1 = *reinterpret_cast<const float4*>(src + base + 4);

    float2* bins = g_bins + row * NUM_LABELS;

    red_sum_count(bins + l0.x, s0.x);
    red_sum_count(bins + l0.y, s0.y);
    red_sum_count(bins + l0.z, s0.z);
    red_sum_count(bins + l0.w, s0.w);
    red_sum_count(bins + l1.x, s1.x);
    red_sum_count(bins + l1.y, s1.y);
    red_sum_count(bins + l1.z, s1.z);
    red_sum_count(bins + l1.w, s1.w);
}

// ---------------------------------------------------------------------------
// Kernel 2: gather. One CTA per row. 512 threads: each computes one segment
// mean into shared, then the CTA streams the row's 65536 labels (int4) and
// writes the means (float4). Empty bins give NaN (0/0) but are never
// gathered: any label present in the row has count >= 1.
// ---------------------------------------------------------------------------
__global__ void __launch_bounds__(512)
sppool_gather(const int* __restrict__ labels, float* __restrict__ out) {
    __shared__ float s_mean[NUM_LABELS];
    const unsigned row = blockIdx.x;
    const unsigned t   = threadIdx.x;

    float2 bc = g_bins[row * NUM_LABELS + t];
    s_mean[t] = bc.x / bc.y;
    __syncthreads();

    const int* lab = labels + (size_t)row * ROW_N;
    float*     o   = out    + (size_t)row * ROW_N;

    #pragma unroll
    for (int i = 0; i < 32; ++i) {
        unsigned idx = (i * 512u + t) * 4u;
        int4 p = *reinterpret_cast<const int4*>(lab + idx);
        float4 v;
        v.x = s_mean[p.x];
        v.y = s_mean[p.y];
        v.z = s_mean[p.z];
        v.w = s_mean[p.w];
        *reinterpret_cast<float4*>(o + idx) = v;
    }
}

// ---------------------------------------------------------------------------
// Launch: zero -> scatter -> gather (stream-ordered, graph-capturable).
// ---------------------------------------------------------------------------
extern "C" void kernel_launch(void* const* d_in, const int* in_sizes, int n_in,
                              void* d_out, int out_size) {
    const float* src    = (const float*)d_in[0];
    const int*   labels = (const int*)d_in[1];
    float*       out    = (float*)d_out;

    sppool_zero_bins<<<(NUM_ROWS * NUM_LABELS + 255) / 256, 256>>>();

    const unsigned n_blocks = TOTAL_ELEMS / SC_CHUNK;        // 16384
    sppool_scatter<<<n_blocks, SC_THREADS>>>(src, labels);

    sppool_gather<<<NUM_ROWS, 512>>>(labels, out);           // 512 blocks
}